// round 9
// baseline (speedup 1.0000x reference)
#include <cuda_runtime.h>
#include <cuda_bf16.h>
#include <cstdint>

#define NN 50000
#define EE 20000
#define MM 320000
#define HH 4
#define KD 256
#define NC 384   // 256 V | 128 hid

// ---------------- static scratch ----------------
__device__ float    g_C[(size_t)NN * NC];
__device__ float    g_h[(size_t)NN * KD];
__device__ float    g_p[NN * 12];
__device__ float    g_aw[MM * 4];
__device__ float    g_ef[(size_t)EE * 256];
__device__ int      g_et[MM];
__device__ int      g_ecnt[EE];
__device__ int      g_estart[EE + 1];
__device__ int      g_ecur[EE];
__device__ int      g_pbe[MM];
__device__ int      g_ncnt[NN];
__device__ int      g_nstart[NN + 1];
__device__ int      g_ncur[NN];
__device__ int      g_pbn[MM];
__device__ float    g_W[NC * KD];
__device__ float    g_stq[HH * 3 * 32];
__device__ float    g_qe[12 * 256];
__device__ int      g_bsum[2][64];

#define MMA16816(d, a, b0, b1) \
  asm volatile("mma.sync.aligned.m16n8k16.row.col.f32.bf16.bf16.f32 " \
    "{%0,%1,%2,%3}, {%4,%5,%6,%7}, {%8,%9}, {%0,%1,%2,%3};" \
    : "+f"((d)[0]), "+f"((d)[1]), "+f"((d)[2]), "+f"((d)[3]) \
    : "r"((a)[0]), "r"((a)[1]), "r"((a)[2]), "r"((a)[3]), "r"(b0), "r"(b1))

__device__ __forceinline__ uint32_t packbf(float x, float y) {
  __nv_bfloat162 p = __float22bfloat162_rn(make_float2(x, y));  // .x -> low half
  return *(uint32_t*)&p;
}

// ---------------- CSR build ----------------
__global__ void zero_counts_kernel() {
  int i = blockIdx.x * blockDim.x + threadIdx.x;
  if (i < EE) g_ecnt[i] = 0;
  if (i < NN) g_ncnt[i] = 0;
}

__global__ void hist_kernel(const int* __restrict__ ni, const int* __restrict__ ei,
                            const int* __restrict__ etype) {
  int m = blockIdx.x * blockDim.x + threadIdx.x;
  if (m >= MM) return;
  int e = ei[m];
  atomicAdd(&g_ecnt[e], 1);
  atomicAdd(&g_ncnt[ni[m]], 1);
  g_et[m] = etype[e];
}

__global__ void scanA_kernel(int which) {
  __shared__ int sh[1024];
  const int* cnt = which ? g_ncnt : g_ecnt;
  int* start = which ? g_nstart : g_estart;
  int n = which ? NN : EE;
  int i = blockIdx.x * 1024 + threadIdx.x;
  int v = (i < n) ? cnt[i] : 0;
  sh[threadIdx.x] = v;
  __syncthreads();
  for (int off = 1; off < 1024; off <<= 1) {
    int t = (threadIdx.x >= (unsigned)off) ? sh[threadIdx.x - off] : 0;
    __syncthreads();
    sh[threadIdx.x] += t;
    __syncthreads();
  }
  if (i < n) start[i] = sh[threadIdx.x] - v;
  if (threadIdx.x == 1023) g_bsum[which][blockIdx.x] = sh[1023];
}

__global__ void scanB_kernel(int which, int nblk) {
  if (threadIdx.x) return;
  int* start = which ? g_nstart : g_estart;
  int n = which ? NN : EE;
  int run = 0;
  for (int b = 0; b < nblk; ++b) { int t = g_bsum[which][b]; g_bsum[which][b] = run; run += t; }
  start[n] = run;
}

__global__ void scanC_kernel(int which) {
  int* start = which ? g_nstart : g_estart;
  int* cur = which ? g_ncur : g_ecur;
  int n = which ? NN : EE;
  int i = blockIdx.x * 1024 + threadIdx.x;
  if (i < n) {
    int s = start[i] + g_bsum[which][blockIdx.x];
    start[i] = s;
    cur[i] = s;
  }
}

__global__ void fill_kernel(const int* __restrict__ ni, const int* __restrict__ ei) {
  int m = blockIdx.x * blockDim.x + threadIdx.x;
  if (m >= MM) return;
  int pe = atomicAdd(&g_ecur[ei[m]], 1);
  g_pbe[pe] = m;
  int pn = atomicAdd(&g_ncur[ni[m]], 1);
  g_pbn[pn] = m;
}

__global__ void segsort_kernel(int which) {
  int s = blockIdx.x * blockDim.x + threadIdx.x;
  const int* start = which ? g_nstart : g_estart;
  int* list = which ? g_pbn : g_pbe;
  int nseg = which ? NN : EE;
  if (s >= nseg) return;
  int a = start[s], b = start[s + 1];
  for (int i = a; i < b - 1; ++i) {
    int mi = i, mv = list[i];
    for (int j = i + 1; j < b; ++j) {
      int v = list[j];
      if (v < mv) { mv = v; mi = j; }
    }
    list[mi] = list[i];
    list[i] = mv;
  }
}

// ---------------- per-layer weight prep ----------------
// qe[h*3+t][c] = sum_o ec[l,h,t,o] * wq[l,h,o,c]
__global__ void qe_kernel(const float* __restrict__ ec, const float* __restrict__ wq, int l) {
  __shared__ float s_ec[64];
  int ht = blockIdx.x;           // 0..11
  int h = ht / 3, t = ht % 3;
  int c = threadIdx.x;           // 0..255
  if (c < 64) s_ec[c] = ec[((l * HH + h) * 3 + t) * 64 + c];
  __syncthreads();
  const float* wr = wq + ((size_t)(l * HH + h) * 64) * 256 + c;
  float s = 0.f;
  for (int d = 0; d < 64; ++d) s += s_ec[d] * wr[(size_t)d * 256];
  g_qe[ht * 256 + c] = s;
}

__global__ void build_w_kernel(const float* __restrict__ wv, const float* __restrict__ w1,
                               int l) {
  int idx = blockIdx.x * blockDim.x + threadIdx.x;
  if (idx >= NC * KD) return;
  int r = idx >> 8, c = idx & 255;
  float v;
  if (r < 256) v = wv[((size_t)l * 256 + r) * 256 + c];
  else {
    int hk = r - 256;
    v = w1[(((size_t)l * HH + (hk >> 5)) * 32 + (hk & 31)) * 320 + c];
  }
  g_W[idx] = v;
}

__global__ void stq_kernel(const float* __restrict__ tq, const float* __restrict__ w1,
                           const float* __restrict__ b1, int l) {
  int tid = threadIdx.x;
  if (tid >= 384) return;
  int h = tid / 96, rem = tid % 96, t = rem / 32, k = rem & 31;
  float s = b1[(l * HH + h) * 32 + k];
  const float* tr = tq + ((l * HH + h) * 3 + t) * 64;
  const float* wr = w1 + (((size_t)l * HH + h) * 32 + k) * 320 + 256;
  for (int d = 0; d < 64; ++d) s += tr[d] * wr[d];
  g_stq[(h * 3 + t) * 32 + k] = s;
}

// ---------------- bf16 mma GEMM: g_C[N,384] = X[N,256] * g_W^T ----------------
// CTA 128(M) x 64(N), 8 warps (4x2), warp tile 32x32, k-chunk 32 (2 mma k16 steps).
// fp32 global loads, convert-to-bf16x2 at SMEM store. Fragment scheme identical to
// the exonerated R7/R8 spec-literal layout; row stride 20 words -> conflict-free.
__global__ __launch_bounds__(256, 2) void gemm_bf16_kernel(const float* __restrict__ xin,
                                                           int l) {
  const float* __restrict__ X = l ? g_h : xin;
  __shared__ uint32_t sA[128][20];  // 16 data words + 4 pad
  __shared__ uint32_t sB[64][20];
  const int tid = threadIdx.x, lane = tid & 31, wid = tid >> 5;
  const int wm = wid >> 1, wn = wid & 1;
  const int g = lane >> 2, tg = lane & 3;
  const int row0 = blockIdx.y * 128, col0 = blockIdx.x * 64;

  float acc[2][4][4];
#pragma unroll
  for (int a = 0; a < 2; ++a)
#pragma unroll
    for (int b = 0; b < 4; ++b)
#pragma unroll
      for (int c = 0; c < 4; ++c) acc[a][b][c] = 0.f;

  float4 pa[4], pb[2];
  // prefetch chunk 0 (A: 128 rows x 8 float4; B: 64 rows x 8 float4)
#pragma unroll
  for (int i = 0; i < 4; ++i) {
    int u = tid + i * 256, r = u >> 3, q = u & 7;
    int gr = row0 + r;
    pa[i] = (gr < NN) ? *(const float4*)(X + (size_t)gr * KD + q * 4)
                      : make_float4(0.f, 0.f, 0.f, 0.f);
  }
#pragma unroll
  for (int i = 0; i < 2; ++i) {
    int u = tid + i * 256, r = u >> 3, q = u & 7;
    pb[i] = *(const float4*)(g_W + (size_t)(col0 + r) * KD + q * 4);
  }

  for (int kc = 0; kc < 8; ++kc) {
#pragma unroll
    for (int i = 0; i < 4; ++i) {
      int u = tid + i * 256, r = u >> 3, q = u & 7;
      sA[r][q * 2]     = packbf(pa[i].x, pa[i].y);
      sA[r][q * 2 + 1] = packbf(pa[i].z, pa[i].w);
    }
#pragma unroll
    for (int i = 0; i < 2; ++i) {
      int u = tid + i * 256, r = u >> 3, q = u & 7;
      sB[r][q * 2]     = packbf(pb[i].x, pb[i].y);
      sB[r][q * 2 + 1] = packbf(pb[i].z, pb[i].w);
    }
    __syncthreads();
    if (kc < 7) {  // prefetch next chunk (overlaps with MMA below)
#pragma unroll
      for (int i = 0; i < 4; ++i) {
        int u = tid + i * 256, r = u >> 3, q = u & 7;
        int gr = row0 + r;
        pa[i] = (gr < NN) ? *(const float4*)(X + (size_t)gr * KD + (kc + 1) * 32 + q * 4)
                          : make_float4(0.f, 0.f, 0.f, 0.f);
      }
#pragma unroll
      for (int i = 0; i < 2; ++i) {
        int u = tid + i * 256, r = u >> 3, q = u & 7;
        pb[i] = *(const float4*)(g_W + (size_t)(col0 + r) * KD + (kc + 1) * 32 + q * 4);
      }
    }
#pragma unroll
    for (int ks = 0; ks < 2; ++ks) {   // two k16 steps cover 32 elems
      const int k0 = ks * 8;           // word offset
      uint32_t af[2][4], bf[4][2];
#pragma unroll
      for (int mt = 0; mt < 2; ++mt) {
        int rowA = wm * 32 + mt * 16 + g;
        af[mt][0] = sA[rowA][k0 + tg];          // k = tg*2..tg*2+1
        af[mt][1] = sA[rowA + 8][k0 + tg];
        af[mt][2] = sA[rowA][k0 + tg + 4];      // k + 8
        af[mt][3] = sA[rowA + 8][k0 + tg + 4];
      }
#pragma unroll
      for (int j = 0; j < 4; ++j) {
        int rowB = wn * 32 + j * 8 + g;
        bf[j][0] = sB[rowB][k0 + tg];
        bf[j][1] = sB[rowB][k0 + tg + 4];
      }
#pragma unroll
      for (int mt = 0; mt < 2; ++mt)
#pragma unroll
        for (int j = 0; j < 4; ++j)
          MMA16816(acc[mt][j], af[mt], bf[j][0], bf[j][1]);
    }
    __syncthreads();
  }

#pragma unroll
  for (int mt = 0; mt < 2; ++mt) {
    int rg = row0 + wm * 32 + mt * 16 + g;
#pragma unroll
    for (int j = 0; j < 4; ++j) {
      int c = col0 + wn * 32 + j * 8 + tg * 2;
      if (rg < NN)
        *(float2*)&g_C[(size_t)rg * NC + c] = make_float2(acc[mt][j][0], acc[mt][j][1]);
      if (rg + 8 < NN)
        *(float2*)&g_C[(size_t)(rg + 8) * NC + c] = make_float2(acc[mt][j][2], acc[mt][j][3]);
    }
  }
}

// ---------------- per-node gate + qe dots -> p[n][t][h] ----------------
__global__ __launch_bounds__(256) void k2_kernel(const float* __restrict__ w2,
                                                 const float* __restrict__ b2,
                                                 const int* __restrict__ node_types,
                                                 const float* __restrict__ xin, int l) {
  __shared__ float s_stq[HH * 3 * 32];
  __shared__ float s_w2[HH * 32];
  __shared__ float s_b2[HH];
  __shared__ float s_qe[12 * 256];
  int tid = threadIdx.x;
  for (int i = tid; i < HH * 3 * 32; i += 256) s_stq[i] = g_stq[i];
  for (int i = tid; i < HH * 32; i += 256) s_w2[i] = w2[l * HH * 32 + i];
  if (tid < HH) s_b2[tid] = b2[l * HH + tid];
  for (int i = tid; i < 12 * 256; i += 256) s_qe[i] = g_qe[i];
  __syncthreads();
  int warp = tid >> 5, lane = tid & 31;
  int n = blockIdx.x * 8 + warp;
  if (n >= NN) return;
  int tn = node_types[n];
  const float* Crow = g_C + (size_t)n * NC;
  const float* hrow = (l ? g_h : xin) + (size_t)n * KD;
  float hr[8];
#pragma unroll
  for (int j = 0; j < 8; ++j) hr[j] = hrow[j * 32 + lane];
#pragma unroll
  for (int h = 0; h < HH; ++h) {
    float hv = Crow[256 + h * 32 + lane];
    float th = tanhf(hv + s_stq[(h * 3 + tn) * 32 + lane]) * s_w2[h * 32 + lane];
#pragma unroll
    for (int o = 16; o; o >>= 1) th += __shfl_xor_sync(0xFFFFFFFFu, th, o);
    float at = 1.f / (1.f + expf(-(th + s_b2[h])));
#pragma unroll
    for (int t = 0; t < 3; ++t) {
      const float* qr = &s_qe[(h * 3 + t) * 256];
      float sp = 0.f;
#pragma unroll
      for (int j = 0; j < 8; ++j) sp += hr[j] * qr[j * 32 + lane];
#pragma unroll
      for (int o = 16; o; o >>= 1) sp += __shfl_xor_sync(0xFFFFFFFFu, sp, o);
      if (lane == 0) {
        float lr = sp > 0.f ? sp : 0.2f * sp;
        g_p[(n * 3 + t) * 4 + h] = lr * at;
      }
    }
  }
}

// ---------------- fused segment softmax + edge_feat gather: warp per edge ----------------
__global__ __launch_bounds__(256) void kE5_kernel(const int* __restrict__ ni) {
  int e = (blockIdx.x * blockDim.x + threadIdx.x) >> 5;
  int lane = threadIdx.x & 31;
  if (e >= EE) return;
  int a = g_estart[e], b = g_estart[e + 1];
  // ---- phase 1: softmax (lane = pair_slot*4 + head; capacity 64 pairs) ----
  {
    int h = lane & 3, pi = lane >> 2;
    float v[8];
    int mm[8];
    float mx = -1e30f;
#pragma unroll
    for (int k = 0; k < 8; ++k) {
      int i = a + k * 8 + pi;
      int m = -1;
      float val = -1e30f;
      if (i < b) {
        m = g_pbe[i];
        int nn2 = ni[m], t = g_et[m];
        val = g_p[(nn2 * 3 + t) * 4 + h];
      }
      mm[k] = m;
      v[k] = val;
      mx = fmaxf(mx, val);
    }
#pragma unroll
    for (int o = 4; o < 32; o <<= 1) mx = fmaxf(mx, __shfl_xor_sync(0xFFFFFFFFu, mx, o));
    float s = 0.f;
#pragma unroll
    for (int k = 0; k < 8; ++k) {
      if (mm[k] >= 0) { v[k] = expf(v[k] - mx); s += v[k]; }
    }
#pragma unroll
    for (int o = 4; o < 32; o <<= 1) s += __shfl_xor_sync(0xFFFFFFFFu, s, o);
    float inv = 1.f / s;
#pragma unroll
    for (int k = 0; k < 8; ++k)
      if (mm[k] >= 0) g_aw[mm[k] * 4 + h] = v[k] * inv;
  }
  __syncwarp();
  // ---- phase 2: gather V rows (lane: hh = lane>>3, c0 = lane*8) ----
  {
    int hh = lane >> 3;
    int c0 = lane * 8;
    float4 a0 = make_float4(0, 0, 0, 0), a1 = make_float4(0, 0, 0, 0);
    for (int i = a; i < b; ++i) {
      int m = g_pbe[i];
      float w = g_aw[m * 4 + hh];
      const float* Vr = g_C + (size_t)ni[m] * NC + c0;
      float4 v0 = *(const float4*)Vr;
      float4 v1 = *(const float4*)(Vr + 4);
      a0.x += w * v0.x; a0.y += w * v0.y; a0.z += w * v0.z; a0.w += w * v0.w;
      a1.x += w * v1.x; a1.y += w * v1.y; a1.z += w * v1.z; a1.w += w * v1.w;
    }
    float* out = g_ef + (size_t)e * 256 + c0;
    *(float4*)out = a0;
    *(float4*)(out + 4) = a1;
  }
}

// ---------------- node_feat + residual + LayerNorm ----------------
__global__ __launch_bounds__(256) void k6_kernel(const int* __restrict__ ei,
                                                 const float* __restrict__ xin,
                                                 const float* __restrict__ ln_g,
                                                 const float* __restrict__ ln_b,
                                                 float* __restrict__ dout, int l) {
  int n = (blockIdx.x * blockDim.x + threadIdx.x) >> 5;
  int lane = threadIdx.x & 31;
  if (n >= NN) return;
  const float* hin = l ? g_h : xin;
  float* hout = l ? dout : g_h;
  int hh = lane >> 3;
  int c0 = lane * 8;
  float v[8];
#pragma unroll
  for (int j = 0; j < 8; ++j) v[j] = 0.f;
  int b = g_nstart[n + 1];
  for (int i = g_nstart[n]; i < b; ++i) {
    int m = g_pbn[i];
    float w = g_aw[m * 4 + hh];
    const float* Er = g_ef + (size_t)ei[m] * 256 + c0;
    float4 e0 = *(const float4*)Er;
    float4 e1 = *(const float4*)(Er + 4);
    v[0] += w * e0.x; v[1] += w * e0.y; v[2] += w * e0.z; v[3] += w * e0.w;
    v[4] += w * e1.x; v[5] += w * e1.y; v[6] += w * e1.z; v[7] += w * e1.w;
  }
  const float* hr = hin + (size_t)n * KD + c0;
#pragma unroll
  for (int j = 0; j < 8; ++j) v[j] += hr[j];
  float s = 0.f;
#pragma unroll
  for (int j = 0; j < 8; ++j) s += v[j];
#pragma unroll
  for (int o = 16; o; o >>= 1) s += __shfl_xor_sync(0xFFFFFFFFu, s, o);
  float mu = s * (1.f / 256.f);
  float vs = 0.f;
#pragma unroll
  for (int j = 0; j < 8; ++j) { float d = v[j] - mu; vs += d * d; }
#pragma unroll
  for (int o = 16; o; o >>= 1) vs += __shfl_xor_sync(0xFFFFFFFFu, vs, o);
  float rs = rsqrtf(vs * (1.f / 256.f) + 1e-5f);
  float o8[8];
#pragma unroll
  for (int j = 0; j < 8; ++j)
    o8[j] = (v[j] - mu) * rs * ln_g[l * KD + c0 + j] + ln_b[l * KD + c0 + j];
  float* op = hout + (size_t)n * KD + c0;
  *(float4*)op = make_float4(o8[0], o8[1], o8[2], o8[3]);
  *(float4*)(op + 4) = make_float4(o8[4], o8[5], o8[6], o8[7]);
}

// ---------------- launcher ----------------
extern "C" void kernel_launch(void* const* d_in, const int* in_sizes, int n_in,
                              void* d_out, int out_size) {
  const float* x          = (const float*)d_in[0];
  const int*   node_types = (const int*)d_in[1];
  const int*   edge_type  = (const int*)d_in[2];
  const int*   node_idx   = (const int*)d_in[3];
  const int*   edge_idx   = (const int*)d_in[4];
  const float* tq         = (const float*)d_in[5];
  const float* w1         = (const float*)d_in[6];
  const float* b1         = (const float*)d_in[7];
  const float* w2         = (const float*)d_in[8];
  const float* b2         = (const float*)d_in[9];
  const float* wq         = (const float*)d_in[10];
  const float* wv         = (const float*)d_in[11];
  const float* ec         = (const float*)d_in[12];
  const float* ln_g       = (const float*)d_in[13];
  const float* ln_b       = (const float*)d_in[14];
  float* out = (float*)d_out;

  const int TB = 256;
  int gMax = (NN + TB - 1) / TB;
  int gM   = (MM + TB - 1) / TB;
  int nbE = (EE + 1023) / 1024, nbN = (NN + 1023) / 1024;

  zero_counts_kernel<<<gMax, TB>>>();
  hist_kernel<<<gM, TB>>>(node_idx, edge_idx, edge_type);
  scanA_kernel<<<nbE, 1024>>>(0);
  scanB_kernel<<<1, 32>>>(0, nbE);
  scanC_kernel<<<nbE, 1024>>>(0);
  scanA_kernel<<<nbN, 1024>>>(1);
  scanB_kernel<<<1, 32>>>(1, nbN);
  scanC_kernel<<<nbN, 1024>>>(1);
  fill_kernel<<<gM, TB>>>(node_idx, edge_idx);
  segsort_kernel<<<(EE + TB - 1) / TB, TB>>>(0);
  segsort_kernel<<<(NN + TB - 1) / TB, TB>>>(1);

  for (int l = 0; l < 2; ++l) {
    qe_kernel<<<12, 256>>>(ec, wq, l);
    build_w_kernel<<<(NC * KD + TB - 1) / TB, TB>>>(wv, w1, l);
    stq_kernel<<<1, 384>>>(tq, w1, b1, l);
    dim3 gg(NC / 64, (NN + 127) / 128);
    gemm_bf16_kernel<<<gg, 256>>>(x, l);
    k2_kernel<<<(NN + 7) / 8, 256>>>(w2, b2, node_types, x, l);
    kE5_kernel<<<(EE + 7) / 8, 256>>>(node_idx);
    k6_kernel<<<(NN + 7) / 8, 256>>>(edge_idx, x, ln_g, ln_b, out, l);
  }
}

// round 10
// speedup vs baseline: 1.3784x; 1.3784x over previous
#include <cuda_runtime.h>
#include <cstdint>

#define NN 50000
#define EE 20000
#define MM 320000
#define HH 4
#define KD 256
#define NC 384   // 256 V | 128 hid

// ---------------- static scratch ----------------
__device__ float    g_C[(size_t)NN * NC];
__device__ float    g_h[(size_t)NN * KD];
__device__ float    g_p[NN * 12];
__device__ float    g_aw[MM * 4];
__device__ float    g_ef[(size_t)EE * 256];
__device__ int      g_et[MM];
__device__ int      g_ecnt[EE];
__device__ int      g_estart[EE + 1];
__device__ int      g_ecur[EE];
__device__ int      g_pbe[MM];
__device__ int      g_ncnt[NN];
__device__ int      g_nstart[NN + 1];
__device__ int      g_ncur[NN];
__device__ int      g_pbn[MM];
__device__ float    g_W[NC * KD];
__device__ float    g_stq[HH * 3 * 32];
__device__ float    g_qe[12 * 256];
__device__ int      g_bsum[2][64];

#define MMATF32(d, a, b0, b1) \
  asm volatile("mma.sync.aligned.m16n8k8.row.col.f32.tf32.tf32.f32 " \
    "{%0,%1,%2,%3}, {%4,%5,%6,%7}, {%8,%9}, {%0,%1,%2,%3};" \
    : "+f"((d)[0]), "+f"((d)[1]), "+f"((d)[2]), "+f"((d)[3]) \
    : "r"((a)[0]), "r"((a)[1]), "r"((a)[2]), "r"((a)[3]), "r"(b0), "r"(b1))

__device__ __forceinline__ uint32_t f2tf32(float x) {
  uint32_t u;
  asm("cvt.rna.tf32.f32 %0, %1;" : "=r"(u) : "f"(x));
  return u;
}

// ---------------- CSR build ----------------
__global__ void zero_counts_kernel() {
  int i = blockIdx.x * blockDim.x + threadIdx.x;
  if (i < EE) g_ecnt[i] = 0;
  if (i < NN) g_ncnt[i] = 0;
}

__global__ void hist_kernel(const int* __restrict__ ni, const int* __restrict__ ei,
                            const int* __restrict__ etype) {
  int m = blockIdx.x * blockDim.x + threadIdx.x;
  if (m >= MM) return;
  int e = ei[m];
  atomicAdd(&g_ecnt[e], 1);
  atomicAdd(&g_ncnt[ni[m]], 1);
  g_et[m] = etype[e];
}

__global__ void scanA_kernel(int which) {
  __shared__ int sh[1024];
  const int* cnt = which ? g_ncnt : g_ecnt;
  int* start = which ? g_nstart : g_estart;
  int n = which ? NN : EE;
  int i = blockIdx.x * 1024 + threadIdx.x;
  int v = (i < n) ? cnt[i] : 0;
  sh[threadIdx.x] = v;
  __syncthreads();
  for (int off = 1; off < 1024; off <<= 1) {
    int t = (threadIdx.x >= (unsigned)off) ? sh[threadIdx.x - off] : 0;
    __syncthreads();
    sh[threadIdx.x] += t;
    __syncthreads();
  }
  if (i < n) start[i] = sh[threadIdx.x] - v;
  if (threadIdx.x == 1023) g_bsum[which][blockIdx.x] = sh[1023];
}

__global__ void scanB_kernel(int which, int nblk) {
  if (threadIdx.x) return;
  int* start = which ? g_nstart : g_estart;
  int n = which ? NN : EE;
  int run = 0;
  for (int b = 0; b < nblk; ++b) { int t = g_bsum[which][b]; g_bsum[which][b] = run; run += t; }
  start[n] = run;
}

__global__ void scanC_kernel(int which) {
  int* start = which ? g_nstart : g_estart;
  int* cur = which ? g_ncur : g_ecur;
  int n = which ? NN : EE;
  int i = blockIdx.x * 1024 + threadIdx.x;
  if (i < n) {
    int s = start[i] + g_bsum[which][blockIdx.x];
    start[i] = s;
    cur[i] = s;
  }
}

__global__ void fill_kernel(const int* __restrict__ ni, const int* __restrict__ ei) {
  int m = blockIdx.x * blockDim.x + threadIdx.x;
  if (m >= MM) return;
  int pe = atomicAdd(&g_ecur[ei[m]], 1);
  g_pbe[pe] = m;
  int pn = atomicAdd(&g_ncur[ni[m]], 1);
  g_pbn[pn] = m;
}

__global__ void segsort_kernel(int which) {
  int s = blockIdx.x * blockDim.x + threadIdx.x;
  const int* start = which ? g_nstart : g_estart;
  int* list = which ? g_pbn : g_pbe;
  int nseg = which ? NN : EE;
  if (s >= nseg) return;
  int a = start[s], b = start[s + 1];
  for (int i = a; i < b - 1; ++i) {
    int mi = i, mv = list[i];
    for (int j = i + 1; j < b; ++j) {
      int v = list[j];
      if (v < mv) { mv = v; mi = j; }
    }
    list[mi] = list[i];
    list[i] = mv;
  }
}

// ---------------- per-layer weight prep (merged qe + stq) ----------------
// blocks 0..11: qe[h*3+t][c] = sum_o ec[l,h,t,o] * wq[l,h,o,c]
// block 12:     stq
__global__ void prep_kernel(const float* __restrict__ ec, const float* __restrict__ wq,
                            const float* __restrict__ tq, const float* __restrict__ w1,
                            const float* __restrict__ b1, int l) {
  int bid = blockIdx.x;
  if (bid < 12) {
    __shared__ float s_ec[64];
    int h = bid / 3, t = bid % 3;
    int c = threadIdx.x;
    if (c < 64) s_ec[c] = ec[((l * HH + h) * 3 + t) * 64 + c];
    __syncthreads();
    if (c < 256) {
      const float* wr = wq + ((size_t)(l * HH + h) * 64) * 256 + c;
      float s = 0.f;
      for (int d = 0; d < 64; ++d) s += s_ec[d] * wr[(size_t)d * 256];
      g_qe[bid * 256 + c] = s;
    }
  } else {
    int tid = threadIdx.x;
    if (tid >= 384) return;
    int h = tid / 96, rem = tid % 96, t = rem / 32, k = rem & 31;
    float s = b1[(l * HH + h) * 32 + k];
    const float* tr = tq + ((l * HH + h) * 3 + t) * 64;
    const float* wr = w1 + (((size_t)l * HH + h) * 32 + k) * 320 + 256;
    for (int d = 0; d < 64; ++d) s += tr[d] * wr[d];
    g_stq[(h * 3 + t) * 32 + k] = s;
  }
}

__global__ void build_w_kernel(const float* __restrict__ wv, const float* __restrict__ w1,
                               int l) {
  int idx = blockIdx.x * blockDim.x + threadIdx.x;
  if (idx >= NC * KD) return;
  int r = idx >> 8, c = idx & 255;
  float v;
  if (r < 256) v = wv[((size_t)l * 256 + r) * 256 + c];
  else {
    int hk = r - 256;
    v = w1[(((size_t)l * HH + (hk >> 5)) * 32 + (hk & 31)) * 320 + c];
  }
  g_W[idx] = v;
}

// ---------------- tf32 mma GEMM: g_C[N,384] = X[N,256] * g_W^T ----------------
// CTA 128(M) x 64(N), 8 warps (4x2), warp tile 32x32, k-chunk 32, double-buffered SMEM.
__global__ __launch_bounds__(256, 2) void gemm_tf32_kernel(const float* __restrict__ xin,
                                                           int l) {
  const float* __restrict__ X = l ? g_h : xin;
  __shared__ uint32_t sA[2][128][36];
  __shared__ uint32_t sB[2][64][36];
  const int tid = threadIdx.x, lane = tid & 31, wid = tid >> 5;
  const int wm = wid >> 1, wn = wid & 1;
  const int g = lane >> 2, tg = lane & 3;
  const int row0 = blockIdx.y * 128, col0 = blockIdx.x * 64;

  float acc[2][4][4];
#pragma unroll
  for (int a = 0; a < 2; ++a)
#pragma unroll
    for (int b = 0; b < 4; ++b)
#pragma unroll
      for (int c = 0; c < 4; ++c) acc[a][b][c] = 0.f;

  float4 pa[4], pb[2];
  // chunk 0 -> regs -> buf 0
#pragma unroll
  for (int i = 0; i < 4; ++i) {
    int u = tid + i * 256, r = u >> 3, q = u & 7;
    int gr = row0 + r;
    pa[i] = (gr < NN) ? *(const float4*)(X + (size_t)gr * KD + q * 4)
                      : make_float4(0.f, 0.f, 0.f, 0.f);
  }
#pragma unroll
  for (int i = 0; i < 2; ++i) {
    int u = tid + i * 256, r = u >> 3, q = u & 7;
    pb[i] = *(const float4*)(g_W + (size_t)(col0 + r) * KD + q * 4);
  }
#pragma unroll
  for (int i = 0; i < 4; ++i) {
    int u = tid + i * 256, r = u >> 3, q = u & 7;
    uint32_t* dst = &sA[0][r][q * 4];
    dst[0] = f2tf32(pa[i].x); dst[1] = f2tf32(pa[i].y);
    dst[2] = f2tf32(pa[i].z); dst[3] = f2tf32(pa[i].w);
  }
#pragma unroll
  for (int i = 0; i < 2; ++i) {
    int u = tid + i * 256, r = u >> 3, q = u & 7;
    uint32_t* dst = &sB[0][r][q * 4];
    dst[0] = f2tf32(pb[i].x); dst[1] = f2tf32(pb[i].y);
    dst[2] = f2tf32(pb[i].z); dst[3] = f2tf32(pb[i].w);
  }
  __syncthreads();

  for (int kc = 0; kc < 8; ++kc) {
    const int buf = kc & 1;
    if (kc < 7) {  // prefetch next chunk into registers (lands during MMA)
#pragma unroll
      for (int i = 0; i < 4; ++i) {
        int u = tid + i * 256, r = u >> 3, q = u & 7;
        int gr = row0 + r;
        pa[i] = (gr < NN) ? *(const float4*)(X + (size_t)gr * KD + (kc + 1) * 32 + q * 4)
                          : make_float4(0.f, 0.f, 0.f, 0.f);
      }
#pragma unroll
      for (int i = 0; i < 2; ++i) {
        int u = tid + i * 256, r = u >> 3, q = u & 7;
        pb[i] = *(const float4*)(g_W + (size_t)(col0 + r) * KD + (kc + 1) * 32 + q * 4);
      }
    }
#pragma unroll
    for (int ks = 0; ks < 4; ++ks) {
      const int k0 = ks * 8;
      uint32_t af[2][4], bf[4][2];
#pragma unroll
      for (int mt = 0; mt < 2; ++mt) {
        int rowA = wm * 32 + mt * 16 + g;
        af[mt][0] = sA[buf][rowA][k0 + tg];
        af[mt][1] = sA[buf][rowA + 8][k0 + tg];
        af[mt][2] = sA[buf][rowA][k0 + tg + 4];
        af[mt][3] = sA[buf][rowA + 8][k0 + tg + 4];
      }
#pragma unroll
      for (int j = 0; j < 4; ++j) {
        int rowB = wn * 32 + j * 8 + g;
        bf[j][0] = sB[buf][rowB][k0 + tg];
        bf[j][1] = sB[buf][rowB][k0 + tg + 4];
      }
#pragma unroll
      for (int mt = 0; mt < 2; ++mt)
#pragma unroll
        for (int j = 0; j < 4; ++j)
          MMATF32(acc[mt][j], af[mt], bf[j][0], bf[j][1]);
    }
    if (kc < 7) {  // store prefetched chunk into the other buffer
#pragma unroll
      for (int i = 0; i < 4; ++i) {
        int u = tid + i * 256, r = u >> 3, q = u & 7;
        uint32_t* dst = &sA[buf ^ 1][r][q * 4];
        dst[0] = f2tf32(pa[i].x); dst[1] = f2tf32(pa[i].y);
        dst[2] = f2tf32(pa[i].z); dst[3] = f2tf32(pa[i].w);
      }
#pragma unroll
      for (int i = 0; i < 2; ++i) {
        int u = tid + i * 256, r = u >> 3, q = u & 7;
        uint32_t* dst = &sB[buf ^ 1][r][q * 4];
        dst[0] = f2tf32(pb[i].x); dst[1] = f2tf32(pb[i].y);
        dst[2] = f2tf32(pb[i].z); dst[3] = f2tf32(pb[i].w);
      }
    }
    __syncthreads();
  }

#pragma unroll
  for (int mt = 0; mt < 2; ++mt) {
    int rg = row0 + wm * 32 + mt * 16 + g;
#pragma unroll
    for (int j = 0; j < 4; ++j) {
      int c = col0 + wn * 32 + j * 8 + tg * 2;
      if (rg < NN)
        *(float2*)&g_C[(size_t)rg * NC + c] = make_float2(acc[mt][j][0], acc[mt][j][1]);
      if (rg + 8 < NN)
        *(float2*)&g_C[(size_t)(rg + 8) * NC + c] = make_float2(acc[mt][j][2], acc[mt][j][3]);
    }
  }
}

// ---------------- per-node gate + qe dots -> p[n][t][h] ----------------
__global__ __launch_bounds__(256) void k2_kernel(const float* __restrict__ w2,
                                                 const float* __restrict__ b2,
                                                 const int* __restrict__ node_types,
                                                 const float* __restrict__ xin, int l) {
  __shared__ float s_stq[HH * 3 * 32];
  __shared__ float s_w2[HH * 32];
  __shared__ float s_b2[HH];
  __shared__ float s_qe[12 * 256];
  int tid = threadIdx.x;
  for (int i = tid; i < HH * 3 * 32; i += 256) s_stq[i] = g_stq[i];
  for (int i = tid; i < HH * 32; i += 256) s_w2[i] = w2[l * HH * 32 + i];
  if (tid < HH) s_b2[tid] = b2[l * HH + tid];
  for (int i = tid; i < 12 * 256; i += 256) s_qe[i] = g_qe[i];
  __syncthreads();
  int warp = tid >> 5, lane = tid & 31;
  int n = blockIdx.x * 8 + warp;
  if (n >= NN) return;
  int tn = node_types[n];
  const float* Crow = g_C + (size_t)n * NC;
  const float* hrow = (l ? g_h : xin) + (size_t)n * KD;
  float hr[8];
#pragma unroll
  for (int j = 0; j < 8; ++j) hr[j] = hrow[j * 32 + lane];
#pragma unroll
  for (int h = 0; h < HH; ++h) {
    float hv = Crow[256 + h * 32 + lane];
    float th = tanhf(hv + s_stq[(h * 3 + tn) * 32 + lane]) * s_w2[h * 32 + lane];
#pragma unroll
    for (int o = 16; o; o >>= 1) th += __shfl_xor_sync(0xFFFFFFFFu, th, o);
    float at = 1.f / (1.f + expf(-(th + s_b2[h])));
#pragma unroll
    for (int t = 0; t < 3; ++t) {
      const float* qr = &s_qe[(h * 3 + t) * 256];
      float sp = 0.f;
#pragma unroll
      for (int j = 0; j < 8; ++j) sp += hr[j] * qr[j * 32 + lane];
#pragma unroll
      for (int o = 16; o; o >>= 1) sp += __shfl_xor_sync(0xFFFFFFFFu, sp, o);
      if (lane == 0) {
        float lr = sp > 0.f ? sp : 0.2f * sp;
        g_p[(n * 3 + t) * 4 + h] = lr * at;
      }
    }
  }
}

// ---------------- segment softmax: warp per edge ----------------
__global__ __launch_bounds__(256) void kE_kernel(const int* __restrict__ ni) {
  int e = (blockIdx.x * blockDim.x + threadIdx.x) >> 5;
  int lane = threadIdx.x & 31;
  if (e >= EE) return;
  int a = g_estart[e], b = g_estart[e + 1];
  int h = lane & 3, pi = lane >> 2;
  float v[8];
  int mm[8];
  float mx = -1e30f;
#pragma unroll
  for (int k = 0; k < 8; ++k) {
    int i = a + k * 8 + pi;
    int m = -1;
    float val = -1e30f;
    if (i < b) {
      m = g_pbe[i];
      int nn2 = ni[m], t = g_et[m];
      val = g_p[(nn2 * 3 + t) * 4 + h];
    }
    mm[k] = m;
    v[k] = val;
    mx = fmaxf(mx, val);
  }
#pragma unroll
  for (int o = 4; o < 32; o <<= 1) mx = fmaxf(mx, __shfl_xor_sync(0xFFFFFFFFu, mx, o));
  float s = 0.f;
#pragma unroll
  for (int k = 0; k < 8; ++k) {
    if (mm[k] >= 0) { v[k] = expf(v[k] - mx); s += v[k]; }
  }
#pragma unroll
  for (int o = 4; o < 32; o <<= 1) s += __shfl_xor_sync(0xFFFFFFFFu, s, o);
  float inv = 1.f / s;
#pragma unroll
  for (int k = 0; k < 8; ++k)
    if (mm[k] >= 0) g_aw[mm[k] * 4 + h] = v[k] * inv;
}

// ---------------- edge_feat: warp per edge, 2x unrolled ----------------
__global__ __launch_bounds__(256) void k5_kernel(const int* __restrict__ ni) {
  int e = (blockIdx.x * blockDim.x + threadIdx.x) >> 5;
  int lane = threadIdx.x & 31;
  if (e >= EE) return;
  int a = g_estart[e], b = g_estart[e + 1];
  int hh = lane >> 3;
  int c0 = lane * 8;
  float4 x0 = make_float4(0, 0, 0, 0), x1 = make_float4(0, 0, 0, 0);
  float4 y0 = make_float4(0, 0, 0, 0), y1 = make_float4(0, 0, 0, 0);
  int i = a;
  for (; i + 1 < b; i += 2) {
    int m0 = g_pbe[i], m1 = g_pbe[i + 1];
    float w0 = g_aw[m0 * 4 + hh], w1 = g_aw[m1 * 4 + hh];
    const float* V0 = g_C + (size_t)ni[m0] * NC + c0;
    const float* V1 = g_C + (size_t)ni[m1] * NC + c0;
    float4 u0 = *(const float4*)V0;
    float4 u1 = *(const float4*)(V0 + 4);
    float4 t0 = *(const float4*)V1;
    float4 t1 = *(const float4*)(V1 + 4);
    x0.x += w0 * u0.x; x0.y += w0 * u0.y; x0.z += w0 * u0.z; x0.w += w0 * u0.w;
    x1.x += w0 * u1.x; x1.y += w0 * u1.y; x1.z += w0 * u1.z; x1.w += w0 * u1.w;
    y0.x += w1 * t0.x; y0.y += w1 * t0.y; y0.z += w1 * t0.z; y0.w += w1 * t0.w;
    y1.x += w1 * t1.x; y1.y += w1 * t1.y; y1.z += w1 * t1.z; y1.w += w1 * t1.w;
  }
  if (i < b) {
    int m0 = g_pbe[i];
    float w0 = g_aw[m0 * 4 + hh];
    const float* V0 = g_C + (size_t)ni[m0] * NC + c0;
    float4 u0 = *(const float4*)V0;
    float4 u1 = *(const float4*)(V0 + 4);
    x0.x += w0 * u0.x; x0.y += w0 * u0.y; x0.z += w0 * u0.z; x0.w += w0 * u0.w;
    x1.x += w0 * u1.x; x1.y += w0 * u1.y; x1.z += w0 * u1.z; x1.w += w0 * u1.w;
  }
  x0.x += y0.x; x0.y += y0.y; x0.z += y0.z; x0.w += y0.w;
  x1.x += y1.x; x1.y += y1.y; x1.z += y1.z; x1.w += y1.w;
  float* out = g_ef + (size_t)e * 256 + c0;
  *(float4*)out = x0;
  *(float4*)(out + 4) = x1;
}

// ---------------- node_feat + residual + LayerNorm, 2x unrolled ----------------
__global__ __launch_bounds__(256) void k6_kernel(const int* __restrict__ ei,
                                                 const float* __restrict__ xin,
                                                 const float* __restrict__ ln_g,
                                                 const float* __restrict__ ln_b,
                                                 float* __restrict__ dout, int l) {
  int n = (blockIdx.x * blockDim.x + threadIdx.x) >> 5;
  int lane = threadIdx.x & 31;
  if (n >= NN) return;
  const float* hin = l ? g_h : xin;
  float* hout = l ? dout : g_h;
  int hh = lane >> 3;
  int c0 = lane * 8;
  float va[8], vb[8];
#pragma unroll
  for (int j = 0; j < 8; ++j) { va[j] = 0.f; vb[j] = 0.f; }
  int a = g_nstart[n], b = g_nstart[n + 1];
  int i = a;
  for (; i + 1 < b; i += 2) {
    int m0 = g_pbn[i], m1 = g_pbn[i + 1];
    float w0 = g_aw[m0 * 4 + hh], w1 = g_aw[m1 * 4 + hh];
    const float* E0 = g_ef + (size_t)ei[m0] * 256 + c0;
    const float* E1 = g_ef + (size_t)ei[m1] * 256 + c0;
    float4 u0 = *(const float4*)E0;
    float4 u1 = *(const float4*)(E0 + 4);
    float4 t0 = *(const float4*)E1;
    float4 t1 = *(const float4*)(E1 + 4);
    va[0] += w0 * u0.x; va[1] += w0 * u0.y; va[2] += w0 * u0.z; va[3] += w0 * u0.w;
    va[4] += w0 * u1.x; va[5] += w0 * u1.y; va[6] += w0 * u1.z; va[7] += w0 * u1.w;
    vb[0] += w1 * t0.x; vb[1] += w1 * t0.y; vb[2] += w1 * t0.z; vb[3] += w1 * t0.w;
    vb[4] += w1 * t1.x; vb[5] += w1 * t1.y; vb[6] += w1 * t1.z; vb[7] += w1 * t1.w;
  }
  if (i < b) {
    int m0 = g_pbn[i];
    float w0 = g_aw[m0 * 4 + hh];
    const float* E0 = g_ef + (size_t)ei[m0] * 256 + c0;
    float4 u0 = *(const float4*)E0;
    float4 u1 = *(const float4*)(E0 + 4);
    va[0] += w0 * u0.x; va[1] += w0 * u0.y; va[2] += w0 * u0.z; va[3] += w0 * u0.w;
    va[4] += w0 * u1.x; va[5] += w0 * u1.y; va[6] += w0 * u1.z; va[7] += w0 * u1.w;
  }
  const float* hr = hin + (size_t)n * KD + c0;
#pragma unroll
  for (int j = 0; j < 8; ++j) va[j] += vb[j] + hr[j];
  float s = 0.f;
#pragma unroll
  for (int j = 0; j < 8; ++j) s += va[j];
#pragma unroll
  for (int o = 16; o; o >>= 1) s += __shfl_xor_sync(0xFFFFFFFFu, s, o);
  float mu = s * (1.f / 256.f);
  float vs = 0.f;
#pragma unroll
  for (int j = 0; j < 8; ++j) { float d = va[j] - mu; vs += d * d; }
#pragma unroll
  for (int o = 16; o; o >>= 1) vs += __shfl_xor_sync(0xFFFFFFFFu, vs, o);
  float rs = rsqrtf(vs * (1.f / 256.f) + 1e-5f);
  float o8[8];
#pragma unroll
  for (int j = 0; j < 8; ++j)
    o8[j] = (va[j] - mu) * rs * ln_g[l * KD + c0 + j] + ln_b[l * KD + c0 + j];
  float* op = hout + (size_t)n * KD + c0;
  *(float4*)op = make_float4(o8[0], o8[1], o8[2], o8[3]);
  *(float4*)(op + 4) = make_float4(o8[4], o8[5], o8[6], o8[7]);
}

// ---------------- launcher ----------------
extern "C" void kernel_launch(void* const* d_in, const int* in_sizes, int n_in,
                              void* d_out, int out_size) {
  const float* x          = (const float*)d_in[0];
  const int*   node_types = (const int*)d_in[1];
  const int*   edge_type  = (const int*)d_in[2];
  const int*   node_idx   = (const int*)d_in[3];
  const int*   edge_idx   = (const int*)d_in[4];
  const float* tq         = (const float*)d_in[5];
  const float* w1         = (const float*)d_in[6];
  const float* b1         = (const float*)d_in[7];
  const float* w2         = (const float*)d_in[8];
  const float* b2         = (const float*)d_in[9];
  const float* wq         = (const float*)d_in[10];
  const float* wv         = (const float*)d_in[11];
  const float* ec         = (const float*)d_in[12];
  const float* ln_g       = (const float*)d_in[13];
  const float* ln_b       = (const float*)d_in[14];
  float* out = (float*)d_out;

  const int TB = 256;
  int gMax = (NN + TB - 1) / TB;
  int gM   = (MM + TB - 1) / TB;
  int nbE = (EE + 1023) / 1024, nbN = (NN + 1023) / 1024;

  zero_counts_kernel<<<gMax, TB>>>();
  hist_kernel<<<gM, TB>>>(node_idx, edge_idx, edge_type);
  scanA_kernel<<<nbE, 1024>>>(0);
  scanB_kernel<<<1, 32>>>(0, nbE);
  scanC_kernel<<<nbE, 1024>>>(0);
  scanA_kernel<<<nbN, 1024>>>(1);
  scanB_kernel<<<1, 32>>>(1, nbN);
  scanC_kernel<<<nbN, 1024>>>(1);
  fill_kernel<<<gM, TB>>>(node_idx, edge_idx);
  segsort_kernel<<<(EE + TB - 1) / TB, TB>>>(0);
  segsort_kernel<<<(NN + TB - 1) / TB, TB>>>(1);

  for (int l = 0; l < 2; ++l) {
    prep_kernel<<<13, 384>>>(ec, wq, tq, w1, b1, l);
    build_w_kernel<<<(NC * KD + TB - 1) / TB, TB>>>(wv, w1, l);
    dim3 gg(NC / 64, (NN + 127) / 128);
    gemm_tf32_kernel<<<gg, 256>>>(x, l);
    k2_kernel<<<(NN + 7) / 8, 256>>>(w2, b2, node_types, x, l);
    kE_kernel<<<(EE + 7) / 8, 256>>>(node_idx);
    k5_kernel<<<(EE + 7) / 8, 256>>>(node_idx);
    k6_kernel<<<(NN + 7) / 8, 256>>>(edge_idx, x, ln_g, ln_b, out, l);
  }
}

// round 11
// speedup vs baseline: 1.5446x; 1.1206x over previous
#include <cuda_runtime.h>
#include <cstdint>

#define NN 50000
#define EE 20000
#define MM 320000
#define HH 4
#define KD 256
#define NC 384   // 256 V | 128 hid

// ---------------- static scratch ----------------
__device__ float    g_C[(size_t)NN * NC];
__device__ float    g_h[(size_t)NN * KD];
__device__ float    g_p[NN * 12];
__device__ float    g_aw[MM * 4];
__device__ float    g_ef[(size_t)EE * 256];
__device__ int      g_et[MM];
__device__ int      g_ecnt[EE];
__device__ int      g_estart[EE + 1];
__device__ int      g_ecur[EE];
__device__ int      g_pbe[MM];
__device__ int      g_ncnt[NN];
__device__ int      g_nstart[NN + 1];
__device__ int      g_ncur[NN];
__device__ int      g_pbn[MM];
__device__ float    g_W[NC * KD];
__device__ float    g_stq[HH * 3 * 32];
__device__ float    g_qe[12 * 256];
__device__ int      g_bsum[2][64];

#define MMATF32(d, a, b0, b1) \
  asm volatile("mma.sync.aligned.m16n8k8.row.col.f32.tf32.tf32.f32 " \
    "{%0,%1,%2,%3}, {%4,%5,%6,%7}, {%8,%9}, {%0,%1,%2,%3};" \
    : "+f"((d)[0]), "+f"((d)[1]), "+f"((d)[2]), "+f"((d)[3]) \
    : "r"((a)[0]), "r"((a)[1]), "r"((a)[2]), "r"((a)[3]), "r"(b0), "r"(b1))

__device__ __forceinline__ uint32_t f2tf32(float x) {
  uint32_t u;
  asm("cvt.rna.tf32.f32 %0, %1;" : "=r"(u) : "f"(x));
  return u;
}

// ---------------- CSR build ----------------
__global__ void zero_counts_kernel() {
  int i = blockIdx.x * blockDim.x + threadIdx.x;
  if (i < EE) g_ecnt[i] = 0;
  if (i < NN) g_ncnt[i] = 0;
}

__global__ void hist_kernel(const int* __restrict__ ni, const int* __restrict__ ei,
                            const int* __restrict__ etype) {
  int m = blockIdx.x * blockDim.x + threadIdx.x;
  if (m >= MM) return;
  int e = ei[m];
  atomicAdd(&g_ecnt[e], 1);
  atomicAdd(&g_ncnt[ni[m]], 1);
  g_et[m] = etype[e];
}

__global__ void scanA_kernel(int which) {
  __shared__ int sh[1024];
  const int* cnt = which ? g_ncnt : g_ecnt;
  int* start = which ? g_nstart : g_estart;
  int n = which ? NN : EE;
  int i = blockIdx.x * 1024 + threadIdx.x;
  int v = (i < n) ? cnt[i] : 0;
  sh[threadIdx.x] = v;
  __syncthreads();
  for (int off = 1; off < 1024; off <<= 1) {
    int t = (threadIdx.x >= (unsigned)off) ? sh[threadIdx.x - off] : 0;
    __syncthreads();
    sh[threadIdx.x] += t;
    __syncthreads();
  }
  if (i < n) start[i] = sh[threadIdx.x] - v;
  if (threadIdx.x == 1023) g_bsum[which][blockIdx.x] = sh[1023];
}

__global__ void scanB_kernel(int which, int nblk) {
  if (threadIdx.x) return;
  int* start = which ? g_nstart : g_estart;
  int n = which ? NN : EE;
  int run = 0;
  for (int b = 0; b < nblk; ++b) { int t = g_bsum[which][b]; g_bsum[which][b] = run; run += t; }
  start[n] = run;
}

__global__ void scanC_kernel(int which) {
  int* start = which ? g_nstart : g_estart;
  int* cur = which ? g_ncur : g_ecur;
  int n = which ? NN : EE;
  int i = blockIdx.x * 1024 + threadIdx.x;
  if (i < n) {
    int s = start[i] + g_bsum[which][blockIdx.x];
    start[i] = s;
    cur[i] = s;
  }
}

__global__ void fill_kernel(const int* __restrict__ ni, const int* __restrict__ ei) {
  int m = blockIdx.x * blockDim.x + threadIdx.x;
  if (m >= MM) return;
  int pe = atomicAdd(&g_ecur[ei[m]], 1);
  g_pbe[pe] = m;
  int pn = atomicAdd(&g_ncur[ni[m]], 1);
  g_pbn[pn] = m;
}

__global__ void segsort_kernel(int which) {
  int s = blockIdx.x * blockDim.x + threadIdx.x;
  const int* start = which ? g_nstart : g_estart;
  int* list = which ? g_pbn : g_pbe;
  int nseg = which ? NN : EE;
  if (s >= nseg) return;
  int a = start[s], b = start[s + 1];
  for (int i = a; i < b - 1; ++i) {
    int mi = i, mv = list[i];
    for (int j = i + 1; j < b; ++j) {
      int v = list[j];
      if (v < mv) { mv = v; mi = j; }
    }
    list[mi] = list[i];
    list[i] = mv;
  }
}

// ---------------- per-layer weight prep (merged qe + stq) ----------------
__global__ void prep_kernel(const float* __restrict__ ec, const float* __restrict__ wq,
                            const float* __restrict__ tq, const float* __restrict__ w1,
                            const float* __restrict__ b1, int l) {
  int bid = blockIdx.x;
  if (bid < 12) {
    __shared__ float s_ec[64];
    int h = bid / 3, t = bid % 3;
    int c = threadIdx.x;
    if (c < 64) s_ec[c] = ec[((l * HH + h) * 3 + t) * 64 + c];
    __syncthreads();
    if (c < 256) {
      const float* wr = wq + ((size_t)(l * HH + h) * 64) * 256 + c;
      float s = 0.f;
      for (int d = 0; d < 64; ++d) s += s_ec[d] * wr[(size_t)d * 256];
      g_qe[bid * 256 + c] = s;
    }
  } else {
    int tid = threadIdx.x;
    if (tid >= 384) return;
    int h = tid / 96, rem = tid % 96, t = rem / 32, k = rem & 31;
    float s = b1[(l * HH + h) * 32 + k];
    const float* tr = tq + ((l * HH + h) * 3 + t) * 64;
    const float* wr = w1 + (((size_t)l * HH + h) * 32 + k) * 320 + 256;
    for (int d = 0; d < 64; ++d) s += tr[d] * wr[d];
    g_stq[(h * 3 + t) * 32 + k] = s;
  }
}

__global__ void build_w_kernel(const float* __restrict__ wv, const float* __restrict__ w1,
                               int l) {
  int idx = blockIdx.x * blockDim.x + threadIdx.x;
  if (idx >= NC * KD) return;
  int r = idx >> 8, c = idx & 255;
  float v;
  if (r < 256) v = wv[((size_t)l * 256 + r) * 256 + c];
  else {
    int hk = r - 256;
    v = w1[(((size_t)l * HH + (hk >> 5)) * 32 + (hk & 31)) * 320 + c];
  }
  g_W[idx] = v;
}

// ---------------- tf32 mma GEMM: g_C[N,384] = X[N,256] * g_W^T ----------------
// CTA 128(M) x 128(N), 8 warps (4x2), warp tile 32x64, k-chunk 32, single buffer.
// A register-prefetched (DRAM-critical); B loaded direct (L2-hot).
__global__ __launch_bounds__(256, 2) void gemm_tf32_kernel(const float* __restrict__ xin,
                                                           int l) {
  const float* __restrict__ X = l ? g_h : xin;
  __shared__ uint32_t sA[128][36];
  __shared__ uint32_t sB[128][36];
  const int tid = threadIdx.x, lane = tid & 31, wid = tid >> 5;
  const int wm = wid >> 1, wn = wid & 1;
  const int g = lane >> 2, tg = lane & 3;
  const int row0 = blockIdx.y * 128, col0 = blockIdx.x * 128;

  float acc[2][8][4];
#pragma unroll
  for (int a = 0; a < 2; ++a)
#pragma unroll
    for (int b = 0; b < 8; ++b)
#pragma unroll
      for (int c = 0; c < 4; ++c) acc[a][b][c] = 0.f;

  float4 pa[4];
  // prefetch A chunk 0
#pragma unroll
  for (int i = 0; i < 4; ++i) {
    int u = tid + i * 256, r = u >> 3, q = u & 7;
    int gr = row0 + r;
    pa[i] = (gr < NN) ? *(const float4*)(X + (size_t)gr * KD + q * 4)
                      : make_float4(0.f, 0.f, 0.f, 0.f);
  }

  for (int kc = 0; kc < 8; ++kc) {
    // store prefetched A
#pragma unroll
    for (int i = 0; i < 4; ++i) {
      int u = tid + i * 256, r = u >> 3, q = u & 7;
      uint32_t* dst = &sA[r][q * 4];
      dst[0] = f2tf32(pa[i].x); dst[1] = f2tf32(pa[i].y);
      dst[2] = f2tf32(pa[i].z); dst[3] = f2tf32(pa[i].w);
    }
    // load B chunk direct (L2-resident weight matrix)
#pragma unroll
    for (int i = 0; i < 4; ++i) {
      int u = tid + i * 256, r = u >> 3, q = u & 7;
      float4 bv = *(const float4*)(g_W + (size_t)(col0 + r) * KD + kc * 32 + q * 4);
      uint32_t* dst = &sB[r][q * 4];
      dst[0] = f2tf32(bv.x); dst[1] = f2tf32(bv.y);
      dst[2] = f2tf32(bv.z); dst[3] = f2tf32(bv.w);
    }
    __syncthreads();
    if (kc < 7) {  // prefetch next A chunk (lands during MMA)
#pragma unroll
      for (int i = 0; i < 4; ++i) {
        int u = tid + i * 256, r = u >> 3, q = u & 7;
        int gr = row0 + r;
        pa[i] = (gr < NN) ? *(const float4*)(X + (size_t)gr * KD + (kc + 1) * 32 + q * 4)
                          : make_float4(0.f, 0.f, 0.f, 0.f);
      }
    }
#pragma unroll
    for (int ks = 0; ks < 4; ++ks) {
      const int k0 = ks * 8;
      uint32_t af[2][4], bf[8][2];
#pragma unroll
      for (int mt = 0; mt < 2; ++mt) {
        int rowA = wm * 32 + mt * 16 + g;
        af[mt][0] = sA[rowA][k0 + tg];
        af[mt][1] = sA[rowA + 8][k0 + tg];
        af[mt][2] = sA[rowA][k0 + tg + 4];
        af[mt][3] = sA[rowA + 8][k0 + tg + 4];
      }
#pragma unroll
      for (int j = 0; j < 8; ++j) {
        int rowB = wn * 64 + j * 8 + g;
        bf[j][0] = sB[rowB][k0 + tg];
        bf[j][1] = sB[rowB][k0 + tg + 4];
      }
#pragma unroll
      for (int mt = 0; mt < 2; ++mt)
#pragma unroll
        for (int j = 0; j < 8; ++j)
          MMATF32(acc[mt][j], af[mt], bf[j][0], bf[j][1]);
    }
    __syncthreads();
  }

#pragma unroll
  for (int mt = 0; mt < 2; ++mt) {
    int rg = row0 + wm * 32 + mt * 16 + g;
#pragma unroll
    for (int j = 0; j < 8; ++j) {
      int c = col0 + wn * 64 + j * 8 + tg * 2;
      if (rg < NN)
        *(float2*)&g_C[(size_t)rg * NC + c] = make_float2(acc[mt][j][0], acc[mt][j][1]);
      if (rg + 8 < NN)
        *(float2*)&g_C[(size_t)(rg + 8) * NC + c] = make_float2(acc[mt][j][2], acc[mt][j][3]);
    }
  }
}

// ---------------- per-node gate + qe dots -> p[n][t][h] ----------------
__global__ __launch_bounds__(256) void k2_kernel(const float* __restrict__ w2,
                                                 const float* __restrict__ b2,
                                                 const int* __restrict__ node_types,
                                                 const float* __restrict__ xin, int l) {
  __shared__ float s_stq[HH * 3 * 32];
  __shared__ float s_w2[HH * 32];
  __shared__ float s_b2[HH];
  __shared__ float s_qe[12 * 256];
  int tid = threadIdx.x;
  for (int i = tid; i < HH * 3 * 32; i += 256) s_stq[i] = g_stq[i];
  for (int i = tid; i < HH * 32; i += 256) s_w2[i] = w2[l * HH * 32 + i];
  if (tid < HH) s_b2[tid] = b2[l * HH + tid];
  for (int i = tid; i < 12 * 256; i += 256) s_qe[i] = g_qe[i];
  __syncthreads();
  int warp = tid >> 5, lane = tid & 31;
  int n = blockIdx.x * 8 + warp;
  if (n >= NN) return;
  int tn = node_types[n];
  const float* Crow = g_C + (size_t)n * NC;
  const float* hrow = (l ? g_h : xin) + (size_t)n * KD;
  float hr[8];
#pragma unroll
  for (int j = 0; j < 8; ++j) hr[j] = hrow[j * 32 + lane];
#pragma unroll
  for (int h = 0; h < HH; ++h) {
    float hv = Crow[256 + h * 32 + lane];
    float th = tanhf(hv + s_stq[(h * 3 + tn) * 32 + lane]) * s_w2[h * 32 + lane];
#pragma unroll
    for (int o = 16; o; o >>= 1) th += __shfl_xor_sync(0xFFFFFFFFu, th, o);
    float at = 1.f / (1.f + expf(-(th + s_b2[h])));
#pragma unroll
    for (int t = 0; t < 3; ++t) {
      const float* qr = &s_qe[(h * 3 + t) * 256];
      float sp = 0.f;
#pragma unroll
      for (int j = 0; j < 8; ++j) sp += hr[j] * qr[j * 32 + lane];
#pragma unroll
      for (int o = 16; o; o >>= 1) sp += __shfl_xor_sync(0xFFFFFFFFu, sp, o);
      if (lane == 0) {
        float lr = sp > 0.f ? sp : 0.2f * sp;
        g_p[(n * 3 + t) * 4 + h] = lr * at;
      }
    }
  }
}

// ---------------- segment softmax: warp per edge ----------------
__global__ __launch_bounds__(256) void kE_kernel(const int* __restrict__ ni) {
  int e = (blockIdx.x * blockDim.x + threadIdx.x) >> 5;
  int lane = threadIdx.x & 31;
  if (e >= EE) return;
  int a = g_estart[e], b = g_estart[e + 1];
  int h = lane & 3, pi = lane >> 2;
  float v[8];
  int mm[8];
  float mx = -1e30f;
#pragma unroll
  for (int k = 0; k < 8; ++k) {
    int i = a + k * 8 + pi;
    int m = -1;
    float val = -1e30f;
    if (i < b) {
      m = g_pbe[i];
      int nn2 = ni[m], t = g_et[m];
      val = g_p[(nn2 * 3 + t) * 4 + h];
    }
    mm[k] = m;
    v[k] = val;
    mx = fmaxf(mx, val);
  }
#pragma unroll
  for (int o = 4; o < 32; o <<= 1) mx = fmaxf(mx, __shfl_xor_sync(0xFFFFFFFFu, mx, o));
  float s = 0.f;
#pragma unroll
  for (int k = 0; k < 8; ++k) {
    if (mm[k] >= 0) { v[k] = expf(v[k] - mx); s += v[k]; }
  }
#pragma unroll
  for (int o = 4; o < 32; o <<= 1) s += __shfl_xor_sync(0xFFFFFFFFu, s, o);
  float inv = 1.f / s;
#pragma unroll
  for (int k = 0; k < 8; ++k)
    if (mm[k] >= 0) g_aw[mm[k] * 4 + h] = v[k] * inv;
}

// ---------------- edge_feat: warp per edge ----------------
__global__ __launch_bounds__(256) void k5_kernel(const int* __restrict__ ni) {
  int e = (blockIdx.x * blockDim.x + threadIdx.x) >> 5;
  int lane = threadIdx.x & 31;
  if (e >= EE) return;
  int a = g_estart[e], b = g_estart[e + 1];
  int hh = lane >> 3;
  int c0 = lane * 8;
  float4 a0 = make_float4(0, 0, 0, 0), a1 = make_float4(0, 0, 0, 0);
  for (int i = a; i < b; ++i) {
    int m = g_pbe[i];
    float w = g_aw[m * 4 + hh];
    const float* Vr = g_C + (size_t)ni[m] * NC + c0;
    float4 v0 = *(const float4*)Vr;
    float4 v1 = *(const float4*)(Vr + 4);
    a0.x += w * v0.x; a0.y += w * v0.y; a0.z += w * v0.z; a0.w += w * v0.w;
    a1.x += w * v1.x; a1.y += w * v1.y; a1.z += w * v1.z; a1.w += w * v1.w;
  }
  float* out = g_ef + (size_t)e * 256 + c0;
  *(float4*)out = a0;
  *(float4*)(out + 4) = a1;
}

// ---------------- node_feat + residual + LayerNorm ----------------
__global__ __launch_bounds__(256) void k6_kernel(const int* __restrict__ ei,
                                                 const float* __restrict__ xin,
                                                 const float* __restrict__ ln_g,
                                                 const float* __restrict__ ln_b,
                                                 float* __restrict__ dout, int l) {
  int n = (blockIdx.x * blockDim.x + threadIdx.x) >> 5;
  int lane = threadIdx.x & 31;
  if (n >= NN) return;
  const float* hin = l ? g_h : xin;
  float* hout = l ? dout : g_h;
  int hh = lane >> 3;
  int c0 = lane * 8;
  float v[8];
#pragma unroll
  for (int j = 0; j < 8; ++j) v[j] = 0.f;
  int b = g_nstart[n + 1];
  for (int i = g_nstart[n]; i < b; ++i) {
    int m = g_pbn[i];
    float w = g_aw[m * 4 + hh];
    const float* Er = g_ef + (size_t)ei[m] * 256 + c0;
    float4 e0 = *(const float4*)Er;
    float4 e1 = *(const float4*)(Er + 4);
    v[0] += w * e0.x; v[1] += w * e0.y; v[2] += w * e0.z; v[3] += w * e0.w;
    v[4] += w * e1.x; v[5] += w * e1.y; v[6] += w * e1.z; v[7] += w * e1.w;
  }
  const float* hr = hin + (size_t)n * KD + c0;
#pragma unroll
  for (int j = 0; j < 8; ++j) v[j] += hr[j];
  float s = 0.f;
#pragma unroll
  for (int j = 0; j < 8; ++j) s += v[j];
#pragma unroll
  for (int o = 16; o; o >>= 1) s += __shfl_xor_sync(0xFFFFFFFFu, s, o);
  float mu = s * (1.f / 256.f);
  float vs = 0.f;
#pragma unroll
  for (int j = 0; j < 8; ++j) { float d = v[j] - mu; vs += d * d; }
#pragma unroll
  for (int o = 16; o; o >>= 1) vs += __shfl_xor_sync(0xFFFFFFFFu, vs, o);
  float rs = rsqrtf(vs * (1.f / 256.f) + 1e-5f);
  float o8[8];
#pragma unroll
  for (int j = 0; j < 8; ++j)
    o8[j] = (v[j] - mu) * rs * ln_g[l * KD + c0 + j] + ln_b[l * KD + c0 + j];
  float* op = hout + (size_t)n * KD + c0;
  *(float4*)op = make_float4(o8[0], o8[1], o8[2], o8[3]);
  *(float4*)(op + 4) = make_float4(o8[4], o8[5], o8[6], o8[7]);
}

// ---------------- launcher ----------------
extern "C" void kernel_launch(void* const* d_in, const int* in_sizes, int n_in,
                              void* d_out, int out_size) {
  const float* x          = (const float*)d_in[0];
  const int*   node_types = (const int*)d_in[1];
  const int*   edge_type  = (const int*)d_in[2];
  const int*   node_idx   = (const int*)d_in[3];
  const int*   edge_idx   = (const int*)d_in[4];
  const float* tq         = (const float*)d_in[5];
  const float* w1         = (const float*)d_in[6];
  const float* b1         = (const float*)d_in[7];
  const float* w2         = (const float*)d_in[8];
  const float* b2         = (const float*)d_in[9];
  const float* wq         = (const float*)d_in[10];
  const float* wv         = (const float*)d_in[11];
  const float* ec         = (const float*)d_in[12];
  const float* ln_g       = (const float*)d_in[13];
  const float* ln_b       = (const float*)d_in[14];
  float* out = (float*)d_out;

  const int TB = 256;
  int gMax = (NN + TB - 1) / TB;
  int gM   = (MM + TB - 1) / TB;
  int nbE = (EE + 1023) / 1024, nbN = (NN + 1023) / 1024;

  zero_counts_kernel<<<gMax, TB>>>();
  hist_kernel<<<gM, TB>>>(node_idx, edge_idx, edge_type);
  scanA_kernel<<<nbE, 1024>>>(0);
  scanB_kernel<<<1, 32>>>(0, nbE);
  scanC_kernel<<<nbE, 1024>>>(0);
  scanA_kernel<<<nbN, 1024>>>(1);
  scanB_kernel<<<1, 32>>>(1, nbN);
  scanC_kernel<<<nbN, 1024>>>(1);
  fill_kernel<<<gM, TB>>>(node_idx, edge_idx);
  segsort_kernel<<<(EE + TB - 1) / TB, TB>>>(0);
  segsort_kernel<<<(NN + TB - 1) / TB, TB>>>(1);

  for (int l = 0; l < 2; ++l) {
    prep_kernel<<<13, 384>>>(ec, wq, tq, w1, b1, l);
    build_w_kernel<<<(NC * KD + TB - 1) / TB, TB>>>(wv, w1, l);
    dim3 gg(NC / 128, (NN + 127) / 128);
    gemm_tf32_kernel<<<gg, 256>>>(x, l);
    k2_kernel<<<(NN + 7) / 8, 256>>>(w2, b2, node_types, x, l);
    kE_kernel<<<(EE + 7) / 8, 256>>>(node_idx);
    k5_kernel<<<(EE + 7) / 8, 256>>>(node_idx);
    k6_kernel<<<(NN + 7) / 8, 256>>>(edge_idx, x, ln_g, ln_b, out, l);
  }
}